// round 14
// baseline (speedup 1.0000x reference)
#include <cuda_runtime.h>
#include <cuda_fp16.h>
#include <cstdint>

// out[b,h] = sum_{d,m} x[b,d,m]*w1[m,h,d]*w2[h,d] + C[h]
//   -> one GEMM: M=256, N=128, K=131072 (k = d*64+m contiguous in x)
//   U[h,k] = w1*w2*256 as single fp16 (err 2^-11); x split exactly fp16 hi+lo
//   out = (xh*U + xl*U)/256 : 2 MMA products.
// R14: 2 CTAs/SM (CTA tile 64x128, 256 thr) so co-resident CTAs hide each
// other's barrier/DRAM latency. Inner loop = proven R8 form (in-reg cvt).
// mma.sync m16n8k16 f16 (tcgen05 unavailable: harness targets compute_103, no 'a').

static constexpr int Ddim = 2048;
static constexpr int Mhist = 64;
static constexpr int Hdim = 128;
static constexpr int KTOT = Ddim * Mhist;     // 131072
static constexpr int KC = 64;                  // K per chunk
static constexpr int NCHUNK = KTOT / KC;       // 2048
static constexpr int KSPLIT = 74;              // grid.x ; grid.y = 4 -> 296 CTAs = 2/SM
static constexpr float USCALE = 256.0f;
static constexpr float UINV = 1.0f / 256.0f;

__device__ __half g_U[(size_t)Hdim * KTOT];    // 32 MB
__device__ float g_C[Hdim];

__device__ __forceinline__ uint32_t smem_u32(const void* p) {
    uint32_t a;
    asm("{ .reg .u64 t; cvta.to.shared.u64 t, %1; cvt.u32.u64 %0, t; }" : "=r"(a) : "l"(p));
    return a;
}
__device__ __forceinline__ uint32_t sw128(uint32_t off) { return off ^ ((off >> 3) & 0x70); }
// fp32 A tile: 256B rows, XOR-swizzle 32B granules by row%8 (conflict-free LDS.64)
__device__ __forceinline__ uint32_t aswz(uint32_t row, uint32_t byte) {
    return row * 256 + (byte ^ ((row & 7) << 5));
}
__device__ __forceinline__ uint32_t h2_bits(__half2 v) {
    return reinterpret_cast<uint32_t&>(v);
}
__device__ __forceinline__ void ldsm_x4(uint32_t& r0, uint32_t& r1, uint32_t& r2, uint32_t& r3,
                                        uint32_t addr) {
    asm volatile("ldmatrix.sync.aligned.m8n8.x4.shared.b16 {%0,%1,%2,%3}, [%4];"
                 : "=r"(r0), "=r"(r1), "=r"(r2), "=r"(r3) : "r"(addr));
}
__device__ __forceinline__ float2 lds64(uint32_t addr) {
    float2 v;
    asm volatile("ld.shared.v2.f32 {%0,%1}, [%2];" : "=f"(v.x), "=f"(v.y) : "r"(addr));
    return v;
}
__device__ __forceinline__ void mma16816(float* c, const uint32_t* a, const uint32_t* b) {
    asm volatile(
        "mma.sync.aligned.m16n8k16.row.col.f32.f16.f16.f32 "
        "{%0,%1,%2,%3}, {%4,%5,%6,%7}, {%8,%9}, {%0,%1,%2,%3};"
        : "+f"(c[0]), "+f"(c[1]), "+f"(c[2]), "+f"(c[3])
        : "r"(a[0]), "r"(a[1]), "r"(a[2]), "r"(a[3]), "r"(b[0]), "r"(b[1]));
}
__device__ __forceinline__ void cp_async16(uint32_t dst, const void* src) {
    asm volatile("cp.async.cg.shared.global [%0], [%1], 16;" :: "r"(dst), "l"(src));
}
#define CP_COMMIT() asm volatile("cp.async.commit_group;" ::: "memory")
#define CP_WAIT_1() asm volatile("cp.async.wait_group 1;" ::: "memory")

// ---------------- precompute ----------------
__global__ void build_u_kernel(const float* __restrict__ w1, const float* __restrict__ w2) {
    int g = blockIdx.x * blockDim.x + threadIdx.x;  // 0 .. 128*2048-1
    int h = g >> 11;
    int d = g & 2047;
    float s = w2[h * Ddim + d] * USCALE;
    uint32_t uu[32];
#pragma unroll 16
    for (int m = 0; m < Mhist; m += 2) {
        float a = w1[((size_t)m * Hdim + h) * Ddim + d] * s;
        float b = w1[((size_t)(m + 1) * Hdim + h) * Ddim + d] * s;
        uu[m >> 1] = h2_bits(__floats2half2_rn(a, b));
    }
    uint4* p = reinterpret_cast<uint4*>(g_U + (size_t)h * KTOT + (size_t)d * Mhist);
#pragma unroll
    for (int j = 0; j < 8; j++) p[j] = reinterpret_cast<uint4*>(uu)[j];
}

__global__ void bias_kernel(const float* __restrict__ b1, const float* __restrict__ w2,
                            const float* __restrict__ b2, float* __restrict__ out) {
    __shared__ float red[256];
    int h = blockIdx.x;
    float s = 0.0f;
    for (int d = threadIdx.x; d < Ddim; d += 256)
        s += b1[h * Ddim + d] * w2[h * Ddim + d];
    red[threadIdx.x] = s;
    __syncthreads();
    for (int st = 128; st > 0; st >>= 1) {
        if (threadIdx.x < st) red[threadIdx.x] += red[threadIdx.x + st];
        __syncthreads();
    }
    __syncthreads();
    float C = red[0] + b2[h];
    out[(size_t)threadIdx.x * Hdim + h] = C;
    if (threadIdx.x == 0) g_C[h] = C;
}

// ---------------- GEMM ----------------
// 256 threads = 8 warps (2x4), CTA tile 64x128, warp tile 32x32.
// stage = {A fp32 16K, B fp16 16K} = 32KB; 3 stages = 96KB; 2 CTAs/SM.
static constexpr int S_B = 16384;
static constexpr int STAGE = 32768;
static constexpr int NSTAGE = 3;
static constexpr int SMEM_TOTAL = NSTAGE * STAGE;  // 98304

__global__ void __launch_bounds__(256, 2)
gemm_kernel(const float* __restrict__ x, float* __restrict__ out) {
    extern __shared__ char smem[];
    uint32_t sb = smem_u32(smem);
    int tid = threadIdx.x;
    int wid = tid >> 5;
    int lane = tid & 31;
    int warp_m = wid >> 2;          // 0..1 (32 rows each)
    int warp_n = wid & 3;           // 0..3 (32 cols each)
    int ksp = blockIdx.x;
    int mtile = blockIdx.y;         // 0..3 (64 rows each)

    int c0 = (ksp * NCHUNK) / KSPLIT;
    int c1 = ((ksp + 1) * NCHUNK) / KSPLIT;

    // A loader: row = tid>>2 (0..63), q = tid&3 (16-col quarter)
    int arow = tid >> 2;
    int q = tid & 3;
    const float* xr = x + ((size_t)(mtile * 64 + arow)) * KTOT + q * 16;
    uint32_t aoA[4];
#pragma unroll
    for (int i = 0; i < 4; i++)
        aoA[i] = aswz((uint32_t)arow, (uint32_t)(q * 64 + i * 16));

    // B loader: row = tid>>1 (0..127), bs = tid&1 (32-col half)
    int brow = tid >> 1;
    int bs = tid & 1;
    const __half* ub = g_U + (size_t)brow * KTOT + bs * 32;
    uint32_t boA[4];
#pragma unroll
    for (int j = 0; j < 4; j++)
        boA[j] = sw128((uint32_t)(brow * 128 + bs * 64 + j * 16));

    // fragment address components
    int rl = lane >> 2;
    uint32_t cxor = (uint32_t)(rl << 5);
    uint32_t cb = (uint32_t)((lane & 3) * 8);
    uint32_t arow0 = (uint32_t)((warp_m * 32 + rl) * 256);
    uint32_t b_row_l = (uint32_t)(warp_n * 32 + ((lane >> 4) << 3) + (lane & 7));
    uint32_t b_kb_l = (uint32_t)(((lane >> 3) & 1) * 16);

    float acc[2][4][4];
#pragma unroll
    for (int i = 0; i < 2; i++)
#pragma unroll
        for (int j = 0; j < 4; j++)
#pragma unroll
            for (int r = 0; r < 4; r++) acc[i][j][r] = 0.0f;

    // ---- prologue: issue 2 stages ----
#pragma unroll
    for (int pi = 0; pi < 2; pi++) {
        int c = c0 + pi;
        uint32_t st = (uint32_t)pi * STAGE;
        const float* xp = xr + (size_t)c * KC;
        const __half* up = ub + (size_t)c * KC;
#pragma unroll
        for (int i = 0; i < 4; i++) cp_async16(sb + st + aoA[i], xp + i * 4);
#pragma unroll
        for (int j = 0; j < 4; j++) cp_async16(sb + st + S_B + boA[j], up + j * 8);
        CP_COMMIT();
    }

    int sidx = 0;                    // stage index of chunk c
    for (int c = c0; c < c1; c++) {
        uint32_t stg = (uint32_t)sidx * STAGE;

        CP_WAIT_1();                 // stage(c) landed (1 newer group may be in flight)
        __syncthreads();             // stage(c) visible; stage((c+2)%3) readers done

        int cn = c + 2;
        if (cn < c1) {
            int nsi = sidx + 2; if (nsi >= 3) nsi -= 3;
            uint32_t nst = (uint32_t)nsi * STAGE;
            const float* xp = xr + (size_t)cn * KC;
            const __half* up = ub + (size_t)cn * KC;
#pragma unroll
            for (int i = 0; i < 4; i++) cp_async16(sb + nst + aoA[i], xp + i * 4);
#pragma unroll
            for (int j = 0; j < 4; j++) cp_async16(sb + nst + S_B + boA[j], up + j * 8);
        }
        CP_COMMIT();                 // uniform group counting

        // ---- MMA on stage(c) (R8 inner loop) ----
        uint32_t Ab = sb + stg;
        uint32_t Bb = sb + stg + S_B;
#pragma unroll
        for (int ks = 0; ks < 4; ks++) {
            uint32_t bh[4][2];
            ldsm_x4(bh[0][0], bh[0][1], bh[1][0], bh[1][1],
                    Bb + sw128(b_row_l * 128 + ks * 32 + b_kb_l));
            ldsm_x4(bh[2][0], bh[2][1], bh[3][0], bh[3][1],
                    Bb + sw128((b_row_l + 16) * 128 + ks * 32 + b_kb_l));
            uint32_t ah[2][4], al[2][4];
#pragma unroll
            for (int mf = 0; mf < 2; mf++) {
                uint32_t base = Ab + arow0 + (uint32_t)(mf * 16 * 256);
                uint32_t c00 = (uint32_t)(ks * 64) + cb;
#pragma unroll
                for (int fi = 0; fi < 4; fi++) {
                    uint32_t addr = base + ((fi & 1) ? 2048u : 0u)
                                  + ((c00 + ((fi >> 1) ? 32u : 0u)) ^ cxor);
                    float2 v = lds64(addr);
                    __half2 H = __floats2half2_rn(v.x, v.y);
                    float2 hf = __half22float2(H);
                    __half2 L = __floats2half2_rn(v.x - hf.x, v.y - hf.y);
                    ah[mf][fi] = h2_bits(H);
                    al[mf][fi] = h2_bits(L);
                }
            }
#pragma unroll
            for (int mf = 0; mf < 2; mf++)
#pragma unroll
                for (int nf = 0; nf < 4; nf++)
                    mma16816(acc[mf][nf], ah[mf], bh[nf]);      // xh * U
#pragma unroll
            for (int mf = 0; mf < 2; mf++)
#pragma unroll
                for (int nf = 0; nf < 4; nf++)
                    mma16816(acc[mf][nf], al[mf], bh[nf]);      // xl * U
        }

        if (++sidx == 3) sidx = 0;
    }

    // ---- epilogue: unscale + split-K atomic reduce (out pre-filled with bias) ----
    int r0 = mtile * 64 + warp_m * 32 + (lane >> 2);
    int cc0 = warp_n * 32 + (lane & 3) * 2;
#pragma unroll
    for (int mf = 0; mf < 2; mf++) {
#pragma unroll
        for (int nf = 0; nf < 4; nf++) {
            int row = r0 + mf * 16;
            int col = cc0 + nf * 8;
            atomicAdd(out + (size_t)row * Hdim + col,           acc[mf][nf][0] * UINV);
            atomicAdd(out + (size_t)row * Hdim + col + 1,       acc[mf][nf][1] * UINV);
            atomicAdd(out + (size_t)(row + 8) * Hdim + col,     acc[mf][nf][2] * UINV);
            atomicAdd(out + (size_t)(row + 8) * Hdim + col + 1, acc[mf][nf][3] * UINV);
        }
    }
}

// ---------------- launch ----------------
extern "C" void kernel_launch(void* const* d_in, const int* in_sizes, int n_in,
                              void* d_out, int out_size) {
    const float* x  = (const float*)d_in[0];
    const float* w1 = (const float*)d_in[1];
    const float* b1 = (const float*)d_in[2];
    const float* w2 = (const float*)d_in[3];
    const float* b2 = (const float*)d_in[4];
    float* out = (float*)d_out;

    cudaFuncSetAttribute(gemm_kernel, cudaFuncAttributeMaxDynamicSharedMemorySize, SMEM_TOTAL);

    build_u_kernel<<<(Hdim * Ddim) / 256, 256>>>(w1, w2);
    bias_kernel<<<Hdim, 256>>>(b1, w2, b2, out);
    dim3 grid(KSPLIT, 4);
    gemm_kernel<<<grid, 256, SMEM_TOTAL>>>(x, out);
}

// round 15
// speedup vs baseline: 1.1115x; 1.1115x over previous
#include <cuda_runtime.h>
#include <cuda_fp16.h>
#include <cstdint>

// out[b,h] = sum_{d,m} x[b,d,m]*w1[m,h,d]*w2[h,d] + C[h]
//   -> one GEMM: M=256, N=128, K=131072 (k = d*64+m contiguous in x)
//   U[h,k] = w1*w2*256 as single fp16 (err 2^-11); x split exactly fp16 hi+lo
//   out = (xh*U + xl*U)/256 : 2 MMA products.
// R15: prep fused (build_u + bias partials + out zeroing) -> 2 launches/call;
// gemm mainloop byte-identical to R8 (best), bias added in ksp==0 epilogue.
// mma.sync m16n8k16 f16 (tcgen05 unavailable: harness targets compute_103, no 'a').

static constexpr int Ddim = 2048;
static constexpr int Mhist = 64;
static constexpr int Hdim = 128;
static constexpr int KTOT = Ddim * Mhist;     // 131072
static constexpr int KC = 64;                  // K per chunk
static constexpr int NCHUNK = KTOT / KC;       // 2048
static constexpr int KSPLIT = 74;              // grid.x ; grid.y = 2 -> 148 CTAs
static constexpr float USCALE = 256.0f;
static constexpr float UINV = 1.0f / 256.0f;

__device__ __half g_U[(size_t)Hdim * KTOT];    // 32 MB
__device__ float g_Cpart[Hdim * 8];            // per-(h, d-slab) bias partials

__device__ __forceinline__ uint32_t smem_u32(const void* p) {
    uint32_t a;
    asm("{ .reg .u64 t; cvta.to.shared.u64 t, %1; cvt.u32.u64 %0, t; }" : "=r"(a) : "l"(p));
    return a;
}
__device__ __forceinline__ uint32_t sw128(uint32_t off) { return off ^ ((off >> 3) & 0x70); }
// fp32 A tile: 256B rows, XOR-swizzle 32B granules by row%8 (conflict-free LDS.64)
__device__ __forceinline__ uint32_t aswz(uint32_t row, uint32_t byte) {
    return row * 256 + (byte ^ ((row & 7) << 5));
}
__device__ __forceinline__ uint32_t h2_bits(__half2 v) {
    return reinterpret_cast<uint32_t&>(v);
}
__device__ __forceinline__ void ldsm_x4(uint32_t& r0, uint32_t& r1, uint32_t& r2, uint32_t& r3,
                                        uint32_t addr) {
    asm volatile("ldmatrix.sync.aligned.m8n8.x4.shared.b16 {%0,%1,%2,%3}, [%4];"
                 : "=r"(r0), "=r"(r1), "=r"(r2), "=r"(r3) : "r"(addr));
}
__device__ __forceinline__ float2 lds64(uint32_t addr) {
    float2 v;
    asm volatile("ld.shared.v2.f32 {%0,%1}, [%2];" : "=f"(v.x), "=f"(v.y) : "r"(addr));
    return v;
}
__device__ __forceinline__ void mma16816(float* c, const uint32_t* a, const uint32_t* b) {
    asm volatile(
        "mma.sync.aligned.m16n8k16.row.col.f32.f16.f16.f32 "
        "{%0,%1,%2,%3}, {%4,%5,%6,%7}, {%8,%9}, {%0,%1,%2,%3};"
        : "+f"(c[0]), "+f"(c[1]), "+f"(c[2]), "+f"(c[3])
        : "r"(a[0]), "r"(a[1]), "r"(a[2]), "r"(a[3]), "r"(b[0]), "r"(b[1]));
}
__device__ __forceinline__ void cp_async16(uint32_t dst, const void* src) {
    asm volatile("cp.async.cg.shared.global [%0], [%1], 16;" :: "r"(dst), "l"(src));
}
#define CP_COMMIT() asm volatile("cp.async.commit_group;" ::: "memory")
#define CP_WAIT_2() asm volatile("cp.async.wait_group 2;" ::: "memory")

// ---------------- prep: build U + bias partials + zero out ----------------
// 1024 blocks x 256 thr. Block b: h = b>>3, d-slab = (b&7)*256.
// Each thread (h,d): 64 strided w1 reads -> one 128B fp16 line of g_U;
// block-reduce b1*w2 -> g_Cpart[b] (plain store: replay-deterministic);
// threads 0..31 zero out[b*32 .. b*32+32).
__global__ void prep_kernel(const float* __restrict__ w1, const float* __restrict__ w2,
                            const float* __restrict__ b1, float* __restrict__ out) {
    __shared__ float red[256];
    int blk = blockIdx.x;
    int t = threadIdx.x;
    int g = blk * 256 + t;
    int h = g >> 11;
    int d = g & 2047;
    float w2v = w2[h * Ddim + d];
    float s = w2v * USCALE;
    uint32_t uu[32];
#pragma unroll 16
    for (int m = 0; m < Mhist; m += 2) {
        float a = w1[((size_t)m * Hdim + h) * Ddim + d] * s;
        float b = w1[((size_t)(m + 1) * Hdim + h) * Ddim + d] * s;
        uu[m >> 1] = h2_bits(__floats2half2_rn(a, b));
    }
    uint4* p = reinterpret_cast<uint4*>(g_U + (size_t)h * KTOT + (size_t)d * Mhist);
#pragma unroll
    for (int j = 0; j < 8; j++) p[j] = reinterpret_cast<uint4*>(uu)[j];

    // bias partial for this block's (h, 256-d slab)
    red[t] = b1[h * Ddim + d] * w2v;
    __syncthreads();
    for (int st = 128; st > 0; st >>= 1) {
        if (t < st) red[t] += red[t + st];
        __syncthreads();
    }
    if (t == 0) g_Cpart[blk] = red[0];

    // zero 32 floats of out
    if (t < 32) out[blk * 32 + t] = 0.0f;
}

// ---------------- GEMM (mainloop identical to R8) ----------------
// 512 threads = 16 warps (4x4), CTA tile 128x128, warp tile 32x32.
// stage = {A fp32 32K, B fp16 16K} = 48KB; 4 stages = 192KB. 3 chunks in flight.
static constexpr int S_B = 32768;
static constexpr int STAGE = 49152;
static constexpr int NSTAGE = 4;
static constexpr int SMEM_TOTAL = NSTAGE * STAGE;  // 196608

__global__ void __launch_bounds__(512, 1)
gemm_kernel(const float* __restrict__ x, const float* __restrict__ b2,
            float* __restrict__ out) {
    extern __shared__ char smem[];
    uint32_t sb = smem_u32(smem);
    int tid = threadIdx.x;
    int wid = tid >> 5;
    int lane = tid & 31;
    int warp_m = wid >> 2;
    int warp_n = wid & 3;
    int ksp = blockIdx.x;
    int mtile = blockIdx.y;

    int c0 = (ksp * NCHUNK) / KSPLIT;
    int c1 = ((ksp + 1) * NCHUNK) / KSPLIT;

    int arow = tid >> 2;
    int q = tid & 3;
    const float* xr = x + ((size_t)(mtile * 128 + arow)) * KTOT + q * 16;
    const __half* ub = g_U + (size_t)arow * KTOT + q * 16;

    uint32_t aoA[4];
#pragma unroll
    for (int i = 0; i < 4; i++)
        aoA[i] = aswz((uint32_t)arow, (uint32_t)(q * 64 + i * 16));
    uint32_t boA[2];
    boA[0] = sw128((uint32_t)(arow * 128 + q * 32));
    boA[1] = sw128((uint32_t)(arow * 128 + q * 32 + 16));

    int rl = lane >> 2;
    uint32_t cxor = (uint32_t)(rl << 5);
    uint32_t cb = (uint32_t)((lane & 3) * 8);
    uint32_t arow0 = (uint32_t)((warp_m * 32 + rl) * 256);
    uint32_t b_row_l = (uint32_t)(warp_n * 32 + ((lane >> 4) << 3) + (lane & 7));
    uint32_t b_kb_l = (uint32_t)(((lane >> 3) & 1) * 16);

    float acc[2][4][4];
#pragma unroll
    for (int i = 0; i < 2; i++)
#pragma unroll
        for (int j = 0; j < 4; j++)
#pragma unroll
            for (int r = 0; r < 4; r++) acc[i][j][r] = 0.0f;

    // ---- prologue: issue 3 stages ----
#pragma unroll
    for (int pi = 0; pi < 3; pi++) {
        int c = c0 + pi;
        uint32_t st = (uint32_t)pi * STAGE;
        const float* xp = xr + (size_t)c * KC;
        const __half* up = ub + (size_t)c * KC;
#pragma unroll
        for (int i = 0; i < 4; i++) cp_async16(sb + st + aoA[i], xp + i * 4);
        cp_async16(sb + st + S_B + boA[0], up);
        cp_async16(sb + st + S_B + boA[1], up + 8);
        CP_COMMIT();
    }

    for (int c = c0; c < c1; c++) {
        uint32_t stg = (uint32_t)((c - c0) & 3) * STAGE;

        CP_WAIT_2();
        __syncthreads();

        int cn = c + 3;
        if (cn < c1) {
            uint32_t nst = (uint32_t)((cn - c0) & 3) * STAGE;
            const float* xp = xr + (size_t)cn * KC;
            const __half* up = ub + (size_t)cn * KC;
#pragma unroll
            for (int i = 0; i < 4; i++) cp_async16(sb + nst + aoA[i], xp + i * 4);
            cp_async16(sb + nst + S_B + boA[0], up);
            cp_async16(sb + nst + S_B + boA[1], up + 8);
        }
        CP_COMMIT();

        uint32_t Ab = sb + stg;
        uint32_t Bb = sb + stg + S_B;
#pragma unroll
        for (int ks = 0; ks < 4; ks++) {
            uint32_t bh[4][2];
            ldsm_x4(bh[0][0], bh[0][1], bh[1][0], bh[1][1],
                    Bb + sw128(b_row_l * 128 + ks * 32 + b_kb_l));
            ldsm_x4(bh[2][0], bh[2][1], bh[3][0], bh[3][1],
                    Bb + sw128((b_row_l + 16) * 128 + ks * 32 + b_kb_l));
            uint32_t ah[2][4], al[2][4];
#pragma unroll
            for (int mf = 0; mf < 2; mf++) {
                uint32_t base = Ab + arow0 + (uint32_t)(mf * 16 * 256);
                uint32_t c00 = (uint32_t)(ks * 64) + cb;
#pragma unroll
                for (int fi = 0; fi < 4; fi++) {
                    uint32_t addr = base + ((fi & 1) ? 2048u : 0u)
                                  + ((c00 + ((fi >> 1) ? 32u : 0u)) ^ cxor);
                    float2 v = lds64(addr);
                    __half2 H = __floats2half2_rn(v.x, v.y);
                    float2 hf = __half22float2(H);
                    __half2 L = __floats2half2_rn(v.x - hf.x, v.y - hf.y);
                    ah[mf][fi] = h2_bits(H);
                    al[mf][fi] = h2_bits(L);
                }
            }
#pragma unroll
            for (int mf = 0; mf < 2; mf++)
#pragma unroll
                for (int nf = 0; nf < 4; nf++)
                    mma16816(acc[mf][nf], ah[mf], bh[nf]);      // xh * U
#pragma unroll
            for (int mf = 0; mf < 2; mf++)
#pragma unroll
                for (int nf = 0; nf < 4; nf++)
                    mma16816(acc[mf][nf], al[mf], bh[nf]);      // xl * U
        }
    }

    // ---- epilogue: unscale + bias (ksp==0 only) + split-K atomic reduce ----
    int r0 = mtile * 128 + warp_m * 32 + (lane >> 2);
    int cc0 = warp_n * 32 + (lane & 3) * 2;
    float Cv[4][2];
#pragma unroll
    for (int nf = 0; nf < 4; nf++) { Cv[nf][0] = 0.0f; Cv[nf][1] = 0.0f; }
    if (ksp == 0) {
#pragma unroll
        for (int nf = 0; nf < 4; nf++) {
#pragma unroll
            for (int u = 0; u < 2; u++) {
                int col = cc0 + nf * 8 + u;
                float cv = b2[col];
#pragma unroll
                for (int sPart = 0; sPart < 8; sPart++)
                    cv += g_Cpart[col * 8 + sPart];
                Cv[nf][u] = cv;
            }
        }
    }
#pragma unroll
    for (int mf = 0; mf < 2; mf++) {
#pragma unroll
        for (int nf = 0; nf < 4; nf++) {
            int row = r0 + mf * 16;
            int col = cc0 + nf * 8;
            atomicAdd(out + (size_t)row * Hdim + col,           acc[mf][nf][0] * UINV + Cv[nf][0]);
            atomicAdd(out + (size_t)row * Hdim + col + 1,       acc[mf][nf][1] * UINV + Cv[nf][1]);
            atomicAdd(out + (size_t)(row + 8) * Hdim + col,     acc[mf][nf][2] * UINV + Cv[nf][0]);
            atomicAdd(out + (size_t)(row + 8) * Hdim + col + 1, acc[mf][nf][3] * UINV + Cv[nf][1]);
        }
    }
}

// ---------------- launch ----------------
extern "C" void kernel_launch(void* const* d_in, const int* in_sizes, int n_in,
                              void* d_out, int out_size) {
    const float* x  = (const float*)d_in[0];
    const float* w1 = (const float*)d_in[1];
    const float* b1 = (const float*)d_in[2];
    const float* w2 = (const float*)d_in[3];
    const float* b2 = (const float*)d_in[4];
    float* out = (float*)d_out;

    cudaFuncSetAttribute(gemm_kernel, cudaFuncAttributeMaxDynamicSharedMemorySize, SMEM_TOTAL);

    prep_kernel<<<(Hdim * Ddim) / 256, 256>>>(w1, w2, b1, out);
    dim3 grid(KSPLIT, 2);
    gemm_kernel<<<grid, 512, SMEM_TOTAL>>>(x, b2, out);
}

// round 17
// speedup vs baseline: 1.3172x; 1.1850x over previous
#include <cuda_runtime.h>
#include <cuda_fp16.h>
#include <cstdint>

// out[b,h] = sum_{d,m} x[b,d,m]*w1[m,h,d]*w2[h,d] + C[h]
//   -> one GEMM: M=256, N=128, K=131072 (k = d*64+m contiguous in x)
//   U[h,k] = w1*w2*256 as fp16 (err 2^-11); x quantized to fp16 in-loop
//   (err 2^-12, combined out rel_err ~2.4e-4 < 1e-3): out = fp16(x)*U/256.
//   SINGLE MMA product per k-step (lo residual dropped -- R16).
// mma.sync m16n8k16 f16 (tcgen05 unavailable: harness targets compute_103, no 'a').

static constexpr int Ddim = 2048;
static constexpr int Mhist = 64;
static constexpr int Hdim = 128;
static constexpr int KTOT = Ddim * Mhist;     // 131072
static constexpr int KC = 64;                  // K per chunk
static constexpr int NCHUNK = KTOT / KC;       // 2048
static constexpr int KSPLIT = 74;              // grid.x ; grid.y = 2 -> 148 CTAs
static constexpr float USCALE = 256.0f;
static constexpr float UINV = 1.0f / 256.0f;

__device__ __half g_U[(size_t)Hdim * KTOT];    // 32 MB
__device__ float g_Cpart[Hdim * 8];            // per-(h, d-slab) bias partials

__device__ __forceinline__ uint32_t smem_u32(const void* p) {
    uint32_t a;
    asm("{ .reg .u64 t; cvta.to.shared.u64 t, %1; cvt.u32.u64 %0, t; }" : "=r"(a) : "l"(p));
    return a;
}
__device__ __forceinline__ uint32_t sw128(uint32_t off) { return off ^ ((off >> 3) & 0x70); }
// fp32 A tile: 256B rows, XOR-swizzle 32B granules by row%8 (conflict-free LDS.64)
__device__ __forceinline__ uint32_t aswz(uint32_t row, uint32_t byte) {
    return row * 256 + (byte ^ ((row & 7) << 5));
}
__device__ __forceinline__ uint32_t h2_bits(__half2 v) {
    return reinterpret_cast<uint32_t&>(v);
}
__device__ __forceinline__ void ldsm_x4(uint32_t& r0, uint32_t& r1, uint32_t& r2, uint32_t& r3,
                                        uint32_t addr) {
    asm volatile("ldmatrix.sync.aligned.m8n8.x4.shared.b16 {%0,%1,%2,%3}, [%4];"
                 : "=r"(r0), "=r"(r1), "=r"(r2), "=r"(r3) : "r"(addr));
}
__device__ __forceinline__ float2 lds64(uint32_t addr) {
    float2 v;
    asm volatile("ld.shared.v2.f32 {%0,%1}, [%2];" : "=f"(v.x), "=f"(v.y) : "r"(addr));
    return v;
}
__device__ __forceinline__ void mma16816(float* c, const uint32_t* a, const uint32_t* b) {
    asm volatile(
        "mma.sync.aligned.m16n8k16.row.col.f32.f16.f16.f32 "
        "{%0,%1,%2,%3}, {%4,%5,%6,%7}, {%8,%9}, {%0,%1,%2,%3};"
        : "+f"(c[0]), "+f"(c[1]), "+f"(c[2]), "+f"(c[3])
        : "r"(a[0]), "r"(a[1]), "r"(a[2]), "r"(a[3]), "r"(b[0]), "r"(b[1]));
}
__device__ __forceinline__ void cp_async16(uint32_t dst, const void* src) {
    asm volatile("cp.async.cg.shared.global [%0], [%1], 16;" :: "r"(dst), "l"(src));
}
#define CP_COMMIT() asm volatile("cp.async.commit_group;" ::: "memory")
#define CP_WAIT_2() asm volatile("cp.async.wait_group 2;" ::: "memory")

// ---------------- prep: build U + bias partials + zero out ----------------
__global__ void prep_kernel(const float* __restrict__ w1, const float* __restrict__ w2,
                            const float* __restrict__ b1, float* __restrict__ out) {
    __shared__ float red[256];
    int blk = blockIdx.x;
    int t = threadIdx.x;
    int g = blk * 256 + t;
    int h = g >> 11;
    int d = g & 2047;
    float w2v = w2[h * Ddim + d];
    float s = w2v * USCALE;
    uint32_t uu[32];
#pragma unroll 16
    for (int m = 0; m < Mhist; m += 2) {
        float a = w1[((size_t)m * Hdim + h) * Ddim + d] * s;
        float b = w1[((size_t)(m + 1) * Hdim + h) * Ddim + d] * s;
        uu[m >> 1] = h2_bits(__floats2half2_rn(a, b));
    }
    uint4* p = reinterpret_cast<uint4*>(g_U + (size_t)h * KTOT + (size_t)d * Mhist);
#pragma unroll
    for (int j = 0; j < 8; j++) p[j] = reinterpret_cast<uint4*>(uu)[j];

    red[t] = b1[h * Ddim + d] * w2v;
    __syncthreads();
    for (int st = 128; st > 0; st >>= 1) {
        if (t < st) red[t] += red[t + st];
        __syncthreads();
    }
    if (t == 0) g_Cpart[blk] = red[0];

    if (t < 32) out[blk * 32 + t] = 0.0f;
}

// ---------------- GEMM ----------------
// 512 threads = 16 warps (4x4), CTA tile 128x128, warp tile 32x32.
// stage = {A fp32 32K, B fp16 16K} = 48KB; 4 stages = 192KB. 3 chunks in flight.
static constexpr int S_B = 32768;
static constexpr int STAGE = 49152;
static constexpr int NSTAGE = 4;
static constexpr int SMEM_TOTAL = NSTAGE * STAGE;  // 196608

__global__ void __launch_bounds__(512, 1)
gemm_kernel(const float* __restrict__ x, const float* __restrict__ b2,
            float* __restrict__ out) {
    extern __shared__ char smem[];
    uint32_t sb = smem_u32(smem);
    int tid = threadIdx.x;
    int wid = tid >> 5;
    int lane = tid & 31;
    int warp_m = wid >> 2;
    int warp_n = wid & 3;
    int ksp = blockIdx.x;
    int mtile = blockIdx.y;

    int c0 = (ksp * NCHUNK) / KSPLIT;
    int c1 = ((ksp + 1) * NCHUNK) / KSPLIT;

    int arow = tid >> 2;
    int q = tid & 3;
    const float* xr = x + ((size_t)(mtile * 128 + arow)) * KTOT + q * 16;
    const __half* ub = g_U + (size_t)arow * KTOT + q * 16;

    uint32_t aoA[4];
#pragma unroll
    for (int i = 0; i < 4; i++)
        aoA[i] = aswz((uint32_t)arow, (uint32_t)(q * 64 + i * 16));
    uint32_t boA[2];
    boA[0] = sw128((uint32_t)(arow * 128 + q * 32));
    boA[1] = sw128((uint32_t)(arow * 128 + q * 32 + 16));

    int rl = lane >> 2;
    uint32_t cxor = (uint32_t)(rl << 5);
    uint32_t cb = (uint32_t)((lane & 3) * 8);
    uint32_t arow0 = (uint32_t)((warp_m * 32 + rl) * 256);
    uint32_t b_row_l = (uint32_t)(warp_n * 32 + ((lane >> 4) << 3) + (lane & 7));
    uint32_t b_kb_l = (uint32_t)(((lane >> 3) & 1) * 16);

    float acc[2][4][4];
#pragma unroll
    for (int i = 0; i < 2; i++)
#pragma unroll
        for (int j = 0; j < 4; j++)
#pragma unroll
            for (int r = 0; r < 4; r++) acc[i][j][r] = 0.0f;

    // ---- prologue: issue 3 stages ----
#pragma unroll
    for (int pi = 0; pi < 3; pi++) {
        int c = c0 + pi;
        uint32_t st = (uint32_t)pi * STAGE;
        const float* xp = xr + (size_t)c * KC;
        const __half* up = ub + (size_t)c * KC;
#pragma unroll
        for (int i = 0; i < 4; i++) cp_async16(sb + st + aoA[i], xp + i * 4);
        cp_async16(sb + st + S_B + boA[0], up);
        cp_async16(sb + st + S_B + boA[1], up + 8);
        CP_COMMIT();
    }

    for (int c = c0; c < c1; c++) {
        uint32_t stg = (uint32_t)((c - c0) & 3) * STAGE;

        CP_WAIT_2();
        __syncthreads();

        int cn = c + 3;
        if (cn < c1) {
            uint32_t nst = (uint32_t)((cn - c0) & 3) * STAGE;
            const float* xp = xr + (size_t)cn * KC;
            const __half* up = ub + (size_t)cn * KC;
#pragma unroll
            for (int i = 0; i < 4; i++) cp_async16(sb + nst + aoA[i], xp + i * 4);
            cp_async16(sb + nst + S_B + boA[0], up);
            cp_async16(sb + nst + S_B + boA[1], up + 8);
        }
        CP_COMMIT();

        // ---- MMA on stage(c): SINGLE product xh * U ----
        uint32_t Ab = sb + stg;
        uint32_t Bb = sb + stg + S_B;
#pragma unroll
        for (int ks = 0; ks < 4; ks++) {
            uint32_t bh[4][2];
            ldsm_x4(bh[0][0], bh[0][1], bh[1][0], bh[1][1],
                    Bb + sw128(b_row_l * 128 + ks * 32 + b_kb_l));
            ldsm_x4(bh[2][0], bh[2][1], bh[3][0], bh[3][1],
                    Bb + sw128((b_row_l + 16) * 128 + ks * 32 + b_kb_l));
            uint32_t ah[2][4];
#pragma unroll
            for (int mf = 0; mf < 2; mf++) {
                uint32_t base = Ab + arow0 + (uint32_t)(mf * 16 * 256);
                uint32_t c00 = (uint32_t)(ks * 64) + cb;
#pragma unroll
                for (int fi = 0; fi < 4; fi++) {
                    uint32_t addr = base + ((fi & 1) ? 2048u : 0u)
                                  + ((c00 + ((fi >> 1) ? 32u : 0u)) ^ cxor);
                    float2 v = lds64(addr);
                    ah[mf][fi] = h2_bits(__floats2half2_rn(v.x, v.y));
                }
            }
#pragma unroll
            for (int mf = 0; mf < 2; mf++)
#pragma unroll
                for (int nf = 0; nf < 4; nf++)
                    mma16816(acc[mf][nf], ah[mf], bh[nf]);      // xh * U
        }
    }

    // ---- epilogue: unscale + bias (ksp==0 only) + split-K atomic reduce ----
    int r0 = mtile * 128 + warp_m * 32 + (lane >> 2);
    int cc0 = warp_n * 32 + (lane & 3) * 2;
    float Cv[4][2];
#pragma unroll
    for (int nf = 0; nf < 4; nf++) { Cv[nf][0] = 0.0f; Cv[nf][1] = 0.0f; }
    if (ksp == 0) {
#pragma unroll
        for (int nf = 0; nf < 4; nf++) {
#pragma unroll
            for (int u = 0; u < 2; u++) {
                int col = cc0 + nf * 8 + u;
                float cv = b2[col];
#pragma unroll
                for (int sPart = 0; sPart < 8; sPart++)
                    cv += g_Cpart[col * 8 + sPart];
                Cv[nf][u] = cv;
            }
        }
    }
#pragma unroll
    for (int mf = 0; mf < 2; mf++) {
#pragma unroll
        for (int nf = 0; nf < 4; nf++) {
            int row = r0 + mf * 16;
            int col = cc0 + nf * 8;
            atomicAdd(out + (size_t)row * Hdim + col,           acc[mf][nf][0] * UINV + Cv[nf][0]);
            atomicAdd(out + (size_t)row * Hdim + col + 1,       acc[mf][nf][1] * UINV + Cv[nf][1]);
            atomicAdd(out + (size_t)(row + 8) * Hdim + col,     acc[mf][nf][2] * UINV + Cv[nf][0]);
            atomicAdd(out + (size_t)(row + 8) * Hdim + col + 1, acc[mf][nf][3] * UINV + Cv[nf][1]);
        }
    }
}

// ---------------- launch ----------------
extern "C" void kernel_launch(void* const* d_in, const int* in_sizes, int n_in,
                              void* d_out, int out_size) {
    const float* x  = (const float*)d_in[0];
    const float* w1 = (const float*)d_in[1];
    const float* b1 = (const float*)d_in[2];
    const float* w2 = (const float*)d_in[3];
    const float* b2 = (const float*)d_in[4];
    float* out = (float*)d_out;

    cudaFuncSetAttribute(gemm_kernel, cudaFuncAttributeMaxDynamicSharedMemorySize, SMEM_TOTAL);

    prep_kernel<<<(Hdim * Ddim) / 256, 256>>>(w1, w2, b1, out);
    dim3 grid(KSPLIT, 2);
    gemm_kernel<<<grid, 512, SMEM_TOTAL>>>(x, b2, out);
}